// round 15
// baseline (speedup 1.0000x reference)
#include <cuda_runtime.h>
#include <cuda_fp16.h>
#include <mma.h>

using namespace nvcuda;

#define N_NODES 100000
#define N_EDGES 1600000

typedef unsigned long long ull;

// ---------------- scratch (__device__ globals; no allocation allowed) ----------------
__device__ float g_deg[N_NODES];
__device__ float g_dis[N_NODES];
__device__ int   g_cnt[N_NODES];
__device__ int   g_rowptr[N_NODES];
__device__ int   g_fill[N_NODES];
__device__ int   g_col[N_EDGES];
__device__ float g_val[N_EDGES];
__device__ int   g_is64;
__device__ int   g_total;
__device__ float g_W45[256 * 3];
__device__ float g_b45[3];
__device__ __half g_hx[(size_t)N_NODES * 128];
__device__ __half g_hA[(size_t)N_NODES * 256];
__device__ __half g_hB[(size_t)N_NODES * 64];
__device__ __half g_hW1[128 * 64];
__device__ __half g_hW2[64 * 128];
__device__ __half g_hW3[128 * 256];
__device__ float4 g_proj[N_NODES];

// ---------------- fused init + dtype detection ----------------
__global__ void k_initdet(const long long* __restrict__ ei) {
    __shared__ int bigfound;
    int i = blockIdx.x * blockDim.x + threadIdx.x;
    if (i < N_NODES) {
        g_deg[i] = 1.0f;
        g_cnt[i] = 0;
    }
    if (blockIdx.x == 0) {
        if (threadIdx.x == 0) { bigfound = 0; g_total = 0; }
        __syncthreads();
        bool big = false;
#pragma unroll
        for (int j = 0; j < 8; j++) {
            ull v = (ull)ei[threadIdx.x * 8 + j];
            if (v >= (ull)N_NODES) big = true;
        }
        if (big) bigfound = 1;
        __syncthreads();
        if (threadIdx.x == 0) g_is64 = bigfound ? 0 : 1;
    }
}

__device__ __forceinline__ void decode_edge(const void* eiv, int e, int& s, int& d) {
    if (g_is64) {
        const long long* ei = (const long long*)eiv;
        s = (int)ei[e];
        d = (int)ei[N_EDGES + e];
    } else {
        const int* ei = (const int*)eiv;
        s = ei[e];
        d = ei[N_EDGES + e];
    }
}

__global__ void k_decdeg(const void* __restrict__ eiv, const float* __restrict__ ew) {
    int e = blockIdx.x * blockDim.x + threadIdx.x;
    if (e >= N_EDGES) return;
    int s, d;
    decode_edge(eiv, e, s, d);
    atomicAdd(&g_deg[d], ew[e]);
    atomicAdd(&g_cnt[d], 1);
}

// fused: dis = rsqrt(deg) AND CSR slot allocation (block scan + 1 atomic per block)
__global__ void k_disalloc() {
    __shared__ int s[256];
    __shared__ int sbase;
    int tid = threadIdx.x;
    int i = blockIdx.x * 256 + tid;
    int c = (i < N_NODES) ? g_cnt[i] : 0;
    if (i < N_NODES) g_dis[i] = rsqrtf(g_deg[i]);
    s[tid] = c;
    __syncthreads();
    for (int off = 1; off < 256; off <<= 1) {
        int t = (tid >= off) ? s[tid - off] : 0;
        __syncthreads();
        s[tid] += t;
        __syncthreads();
    }
    if (tid == 255) sbase = atomicAdd(&g_total, s[255]);
    __syncthreads();
    if (i < N_NODES) {
        int r = sbase + s[tid] - c;
        g_rowptr[i] = r;
        g_fill[i] = r;
    }
}

__global__ void k_build(const void* __restrict__ eiv, const float* __restrict__ ew) {
    int e = blockIdx.x * blockDim.x + threadIdx.x;
    if (e >= N_EDGES) return;
    int s, d;
    decode_edge(eiv, e, s, d);
    float nm = g_dis[s] * ew[e] * g_dis[d];
    int p = atomicAdd(&g_fill[d], 1);
    g_col[p] = s;
    g_val[p] = nm;
}

// parallel fold: W45[k][c] = sum_j W4[k][j] * Wout[j][c]; one warp per output
__global__ void k_w45(const float* __restrict__ W4, const float* __restrict__ b4,
                      const float* __restrict__ Wout, const float* __restrict__ bout) {
    int gw = (blockIdx.x * blockDim.x + threadIdx.x) >> 5;
    int lane = threadIdx.x & 31;
    if (gw < 768) {
        int k = gw / 3, c = gw % 3;
        float s = 0.f;
#pragma unroll
        for (int j = lane; j < 256; j += 32)
            s += W4[k * 256 + j] * Wout[j * 3 + c];
#pragma unroll
        for (int off = 16; off; off >>= 1)
            s += __shfl_down_sync(0xffffffffu, s, off);
        if (lane == 0) g_W45[gw] = s;
    } else if (gw < 771) {
        int c = gw - 768;
        float s = 0.f;
#pragma unroll
        for (int j = lane; j < 256; j += 32)
            s += b4[j] * Wout[j * 3 + c];
#pragma unroll
        for (int off = 16; off; off >>= 1)
            s += __shfl_down_sync(0xffffffffu, s, off);
        if (lane == 0) g_b45[c] = s + bout[c];
    }
}

// ---------------- fused fp32->fp16: x (12.8M) then W1/W2/W3 (49152) ----------------
#define NX (N_NODES * 128)
__global__ void k_cvtall(const float* __restrict__ x, const float* __restrict__ W1,
                         const float* __restrict__ W2, const float* __restrict__ W3,
                         __half* __restrict__ hx, __half* __restrict__ h1,
                         __half* __restrict__ h2, __half* __restrict__ h3) {
    int i = (blockIdx.x * blockDim.x + threadIdx.x) * 8;
    const float* in;
    __half* out;
    if (i < NX) { in = x; out = hx; }
    else {
        int w = i - NX;
        if (w < 8192) { in = W1; out = h1; i = w; }
        else if (w < 16384) { in = W2; out = h2; i = w - 8192; }
        else if (w < 49152) { in = W3; out = h3; i = w - 16384; }
        else return;
    }
    float4 a = *(const float4*)&in[i];
    float4 b = *(const float4*)&in[i + 4];
    __half2 q0 = __floats2half2_rn(a.x, a.y);
    __half2 q1 = __floats2half2_rn(a.z, a.w);
    __half2 q2 = __floats2half2_rn(b.x, b.y);
    __half2 q3 = __floats2half2_rn(b.z, b.w);
    uint4 pk;
    pk.x = *(unsigned*)&q0; pk.y = *(unsigned*)&q1;
    pk.z = *(unsigned*)&q2; pk.w = *(unsigned*)&q3;
    *(uint4*)&out[i] = pk;
}

// ---------------- HMMA GEMM (wmma): double-buffered, BK=32, fp16 output (GEMM1 only) ----------------
__global__ void k_hgemm(const __half* __restrict__ A, const __half* __restrict__ W,
                        const float* __restrict__ bias, __half* __restrict__ C,
                        int din, int dout, int relu) {
    __shared__ __half As[2][128][40];
    __shared__ __half Bs[2][32][72];
    __shared__ float Es[8][256];

    int tid = threadIdx.x;
    int lane = tid & 31;
    int wid = tid >> 5;
    int warp_m = wid & 3;
    int warp_n = wid >> 2;
    int row0 = blockIdx.x * 128;
    int col0 = blockIdx.y * 64;

    int ar0 = tid >> 1, ac0 = (tid & 1) * 8;
    int br = tid >> 3, bc = (tid & 7) * 8;

    wmma::fragment<wmma::accumulator, 16, 16, 16, float> acc[2][2];
#pragma unroll
    for (int i = 0; i < 2; i++)
#pragma unroll
        for (int j = 0; j < 2; j++) wmma::fill_fragment(acc[i][j], 0.f);

    int nk = din >> 5;

    {
        uint4 v0 = make_uint4(0, 0, 0, 0), v1 = v0;
        if (row0 + ar0 < N_NODES) {
            v0 = *(const uint4*)&A[(size_t)(row0 + ar0) * din + ac0];
            v1 = *(const uint4*)&A[(size_t)(row0 + ar0) * din + ac0 + 16];
        }
        *(uint4*)&As[0][ar0][ac0] = v0;
        *(uint4*)&As[0][ar0][ac0 + 16] = v1;
        *(uint4*)&Bs[0][br][bc] = *(const uint4*)&W[(size_t)br * dout + col0 + bc];
    }
    __syncthreads();

    for (int kt = 0; kt < nk; kt++) {
        int cur = kt & 1;
        bool more = (kt + 1 < nk);
        uint4 p0, p1, pb;
        if (more) {
            int k0 = (kt + 1) << 5;
            p0 = make_uint4(0, 0, 0, 0); p1 = p0;
            if (row0 + ar0 < N_NODES) {
                p0 = *(const uint4*)&A[(size_t)(row0 + ar0) * din + k0 + ac0];
                p1 = *(const uint4*)&A[(size_t)(row0 + ar0) * din + k0 + ac0 + 16];
            }
            pb = *(const uint4*)&W[(size_t)(k0 + br) * dout + col0 + bc];
        }
#pragma unroll
        for (int ks = 0; ks < 2; ks++) {
            wmma::fragment<wmma::matrix_a, 16, 16, 16, __half, wmma::row_major> af[2];
            wmma::fragment<wmma::matrix_b, 16, 16, 16, __half, wmma::row_major> bf[2];
#pragma unroll
            for (int i = 0; i < 2; i++)
                wmma::load_matrix_sync(af[i], &As[cur][warp_m * 32 + i * 16][ks * 16], 40);
#pragma unroll
            for (int j = 0; j < 2; j++)
                wmma::load_matrix_sync(bf[j], &Bs[cur][ks * 16][warp_n * 32 + j * 16], 72);
#pragma unroll
            for (int i = 0; i < 2; i++)
#pragma unroll
                for (int j = 0; j < 2; j++)
                    wmma::mma_sync(acc[i][j], af[i], bf[j], acc[i][j]);
        }
        if (more) {
            int nxt = cur ^ 1;
            *(uint4*)&As[nxt][ar0][ac0] = p0;
            *(uint4*)&As[nxt][ar0][ac0 + 16] = p1;
            *(uint4*)&Bs[nxt][br][bc] = pb;
            __syncthreads();
        }
    }

#pragma unroll
    for (int i = 0; i < 2; i++) {
#pragma unroll
        for (int j = 0; j < 2; j++) {
            wmma::store_matrix_sync(&Es[wid][0], acc[i][j], 16, wmma::mem_row_major);
            __syncwarp();
            int r = lane >> 1, c = (lane & 1) * 8;
            int gr = row0 + warp_m * 32 + i * 16 + r;
            int gc = col0 + warp_n * 32 + j * 16 + c;
            if (gr < N_NODES) {
                float v[8];
#pragma unroll
                for (int t = 0; t < 8; t++) {
                    float f = Es[wid][r * 16 + c + t];
                    if (bias) f += bias[gc + t];
                    if (relu) f = fmaxf(f, 0.f);
                    v[t] = f;
                }
                __half2 h0 = __floats2half2_rn(v[0], v[1]);
                __half2 h1 = __floats2half2_rn(v[2], v[3]);
                __half2 h2 = __floats2half2_rn(v[4], v[5]);
                __half2 h3 = __floats2half2_rn(v[6], v[7]);
                uint4 pk;
                pk.x = *(unsigned*)&h0; pk.y = *(unsigned*)&h1;
                pk.z = *(unsigned*)&h2; pk.w = *(unsigned*)&h3;
                *(uint4*)&C[(size_t)gr * dout + gc] = pk;
            }
            __syncwarp();
        }
    }
}

// ---------------- aggregation D=64 fp16: 4 edges per warp (L1 only) ----------------
template <bool BIAS, bool RELU>
__global__ void k_agg64(const __half* __restrict__ H, const float* __restrict__ bias,
                        __half* __restrict__ out) {
    int warp = (blockIdx.x * blockDim.x + threadIdx.x) >> 5;
    int lane = threadIdx.x & 31;
    if (warp >= N_NODES) return;
    int grp = lane >> 3, gl = lane & 7;
    const uint4* H4 = (const uint4*)H;

    float a[8];
#pragma unroll
    for (int j = 0; j < 8; j++) a[j] = 0.f;

    if (grp == 0) {
        float selfn = g_dis[warp];
        selfn *= selfn;
        uint4 v = H4[(size_t)warp * 8 + gl];
        const __half2* h2 = (const __half2*)&v;
#pragma unroll
        for (int j = 0; j < 4; j++) {
            float2 f = __half22float2(h2[j]);
            a[2 * j] = f.x * selfn;
            a[2 * j + 1] = f.y * selfn;
        }
    }

    int s = g_rowptr[warp];
    int e = s + g_cnt[warp];
    for (int p = s + grp; p < e; p += 4) {
        int src = __ldg(&g_col[p]);
        float w = __ldg(&g_val[p]);
        uint4 v = __ldg(&H4[(size_t)src * 8 + gl]);
        const __half2* h2 = (const __half2*)&v;
#pragma unroll
        for (int j = 0; j < 4; j++) {
            float2 f = __half22float2(h2[j]);
            a[2 * j] += f.x * w;
            a[2 * j + 1] += f.y * w;
        }
    }
    __syncwarp();
#pragma unroll
    for (int j = 0; j < 8; j++) {
        a[j] += __shfl_xor_sync(0xffffffffu, a[j], 8);
        a[j] += __shfl_xor_sync(0xffffffffu, a[j], 16);
    }
    if (grp == 0) {
#pragma unroll
        for (int j = 0; j < 8; j++) {
            if (BIAS) a[j] += bias[gl * 8 + j];
            if (RELU) a[j] = fmaxf(a[j], 0.f);
        }
        __half2 h0 = __floats2half2_rn(a[0], a[1]);
        __half2 h1 = __floats2half2_rn(a[2], a[3]);
        __half2 h2o = __floats2half2_rn(a[4], a[5]);
        __half2 h3 = __floats2half2_rn(a[6], a[7]);
        uint4 pk;
        pk.x = *(unsigned*)&h0; pk.y = *(unsigned*)&h1;
        pk.z = *(unsigned*)&h2o; pk.w = *(unsigned*)&h3;
        ((uint4*)out)[(size_t)warp * 8 + gl] = pk;
    }
}

// ---------------- FUSED L2: agg64(h1) -> smem A tile -> GEMM2 (128x128) ----------------
__global__ void k_agg_gemm2(const __half* __restrict__ H, const float* __restrict__ bias,
                            __half* __restrict__ C) {
    __shared__ __half As[128][72];   // gathered A tile, D=64 + 8 pad
    __shared__ __half Bs[64][72];    // W2 half: 64 k x 64 n + pad
    __shared__ float Es[8][256];

    int tid = threadIdx.x, lane = tid & 31, wid = tid >> 5;
    int row0 = blockIdx.x * 128;
    int grp = lane >> 3, gl = lane & 7;
    const uint4* H4 = (const uint4*)H;

    // Phase 1: gather 128 rows (warp-per-node pattern, 16 rows per warp)
    for (int r = wid; r < 128; r += 8) {
        int node = row0 + r;
        float a[8];
#pragma unroll
        for (int j = 0; j < 8; j++) a[j] = 0.f;
        if (node < N_NODES) {
            if (grp == 0) {
                float selfn = g_dis[node];
                selfn *= selfn;
                uint4 v = H4[(size_t)node * 8 + gl];
                const __half2* h2 = (const __half2*)&v;
#pragma unroll
                for (int j = 0; j < 4; j++) {
                    float2 f = __half22float2(h2[j]);
                    a[2 * j] = f.x * selfn;
                    a[2 * j + 1] = f.y * selfn;
                }
            }
            int s = g_rowptr[node];
            int e = s + g_cnt[node];
            for (int p = s + grp; p < e; p += 4) {
                int src = __ldg(&g_col[p]);
                float w = __ldg(&g_val[p]);
                uint4 v = __ldg(&H4[(size_t)src * 8 + gl]);
                const __half2* h2 = (const __half2*)&v;
#pragma unroll
                for (int j = 0; j < 4; j++) {
                    float2 f = __half22float2(h2[j]);
                    a[2 * j] += f.x * w;
                    a[2 * j + 1] += f.y * w;
                }
            }
        }
        __syncwarp();
#pragma unroll
        for (int j = 0; j < 8; j++) {
            a[j] += __shfl_xor_sync(0xffffffffu, a[j], 8);
            a[j] += __shfl_xor_sync(0xffffffffu, a[j], 16);
        }
        if (grp == 0) {
            __half2 h0 = __floats2half2_rn(a[0], a[1]);
            __half2 h1 = __floats2half2_rn(a[2], a[3]);
            __half2 h2o = __floats2half2_rn(a[4], a[5]);
            __half2 h3 = __floats2half2_rn(a[6], a[7]);
            uint4 pk;
            pk.x = *(unsigned*)&h0; pk.y = *(unsigned*)&h1;
            pk.z = *(unsigned*)&h2o; pk.w = *(unsigned*)&h3;
            *(uint4*)&As[r][gl * 8] = pk;
        }
    }
    __syncthreads();

    // Phase 2: GEMM 128x128 = As(128x64) @ W2(64x128), two 64-col halves
    int warp_m = wid & 3, warp_n = wid >> 2;
#pragma unroll
    for (int hblk = 0; hblk < 2; hblk++) {
        int n0 = hblk * 64;
        for (int t = tid; t < 512; t += 256) {
            int r = t >> 3, c = (t & 7) * 8;
            *(uint4*)&Bs[r][c] = *(const uint4*)&g_hW2[r * 128 + n0 + c];
        }
        __syncthreads();

        wmma::fragment<wmma::accumulator, 16, 16, 16, float> acc[2][2];
#pragma unroll
        for (int i = 0; i < 2; i++)
#pragma unroll
            for (int j = 0; j < 2; j++) wmma::fill_fragment(acc[i][j], 0.f);

#pragma unroll
        for (int k = 0; k < 4; k++) {
            wmma::fragment<wmma::matrix_a, 16, 16, 16, __half, wmma::row_major> af[2];
            wmma::fragment<wmma::matrix_b, 16, 16, 16, __half, wmma::row_major> bf[2];
#pragma unroll
            for (int i = 0; i < 2; i++)
                wmma::load_matrix_sync(af[i], &As[warp_m * 32 + i * 16][k * 16], 72);
#pragma unroll
            for (int j = 0; j < 2; j++)
                wmma::load_matrix_sync(bf[j], &Bs[k * 16][warp_n * 32 + j * 16], 72);
#pragma unroll
            for (int i = 0; i < 2; i++)
#pragma unroll
                for (int j = 0; j < 2; j++)
                    wmma::mma_sync(acc[i][j], af[i], bf[j], acc[i][j]);
        }

#pragma unroll
        for (int i = 0; i < 2; i++) {
#pragma unroll
            for (int j = 0; j < 2; j++) {
                wmma::store_matrix_sync(&Es[wid][0], acc[i][j], 16, wmma::mem_row_major);
                __syncwarp();
                int r = lane >> 1, c = (lane & 1) * 8;
                int gr = row0 + warp_m * 32 + i * 16 + r;
                int gc = n0 + warp_n * 32 + j * 16 + c;
                if (gr < N_NODES) {
                    float v[8];
#pragma unroll
                    for (int t = 0; t < 8; t++) {
                        float f = Es[wid][r * 16 + c + t] + bias[gc + t];
                        v[t] = fmaxf(f, 0.f);
                    }
                    __half2 h0 = __floats2half2_rn(v[0], v[1]);
                    __half2 h1 = __floats2half2_rn(v[2], v[3]);
                    __half2 h2 = __floats2half2_rn(v[4], v[5]);
                    __half2 h3 = __floats2half2_rn(v[6], v[7]);
                    uint4 pk;
                    pk.x = *(unsigned*)&h0; pk.y = *(unsigned*)&h1;
                    pk.z = *(unsigned*)&h2; pk.w = *(unsigned*)&h3;
                    *(uint4*)&C[(size_t)gr * 128 + gc] = pk;
                }
                __syncwarp();
            }
        }
        __syncthreads();   // Bs reused next half
    }
}

// ---------------- FUSED L3: agg128(t2) -> smem A -> GEMM3 + projection -> g_proj ----------------
// dynamic smem layout: As 128x136 half (34816) | Bs 32x72 half (4608) | Es 8x256 f32 (8192) | proj 128x3 f32 (1536) = 49152
__global__ void k_agg_gemm3proj(const __half* __restrict__ H, const float* __restrict__ bias) {
    extern __shared__ char dyn[];
    __half (*As)[136] = (__half(*)[136])dyn;
    __half (*Bs)[72]  = (__half(*)[72])(dyn + 34816);
    float (*Es)[256]  = (float(*)[256])(dyn + 39424);
    float* proj       = (float*)(dyn + 47616);

    int tid = threadIdx.x, lane = tid & 31, wid = tid >> 5;
    int row0 = blockIdx.x * 128;
    int half_ = lane >> 4, hl = lane & 15;
    const uint4* H4 = (const uint4*)H;

    for (int t = tid; t < 384; t += 256) proj[t] = 0.f;

    // Phase 1: gather 128 rows at D=128 (agg128 pattern, 16 rows per warp)
    for (int r = wid; r < 128; r += 8) {
        int node = row0 + r;
        float a[8];
#pragma unroll
        for (int j = 0; j < 8; j++) a[j] = 0.f;
        if (node < N_NODES) {
            if (half_ == 0) {
                float selfn = g_dis[node];
                selfn *= selfn;
                uint4 v = H4[(size_t)node * 16 + hl];
                const __half2* h2 = (const __half2*)&v;
#pragma unroll
                for (int j = 0; j < 4; j++) {
                    float2 f = __half22float2(h2[j]);
                    a[2 * j] = f.x * selfn;
                    a[2 * j + 1] = f.y * selfn;
                }
            }
            int s = g_rowptr[node];
            int e = s + g_cnt[node];
            for (int p = s + half_; p < e; p += 2) {
                int src = __ldg(&g_col[p]);
                float w = __ldg(&g_val[p]);
                uint4 v = __ldg(&H4[(size_t)src * 16 + hl]);
                const __half2* h2 = (const __half2*)&v;
#pragma unroll
                for (int j = 0; j < 4; j++) {
                    float2 f = __half22float2(h2[j]);
                    a[2 * j] += f.x * w;
                    a[2 * j + 1] += f.y * w;
                }
            }
        }
        __syncwarp();
#pragma unroll
        for (int j = 0; j < 8; j++)
            a[j] += __shfl_xor_sync(0xffffffffu, a[j], 16);
        if (half_ == 0) {
            __half2 h0 = __floats2half2_rn(a[0], a[1]);
            __half2 h1 = __floats2half2_rn(a[2], a[3]);
            __half2 h2o = __floats2half2_rn(a[4], a[5]);
            __half2 h3 = __floats2half2_rn(a[6], a[7]);
            uint4 pk;
            pk.x = *(unsigned*)&h0; pk.y = *(unsigned*)&h1;
            pk.z = *(unsigned*)&h2o; pk.w = *(unsigned*)&h3;
            *(uint4*)&As[r][hl * 8] = pk;
        }
    }
    __syncthreads();

    // Phase 2: GEMM 128x256 (4 slabs of 64 cols), project epilogue into smem proj
    int warp_m = wid & 3, warp_n = wid >> 2;
    int r_ = lane >> 1, cb = (lane & 1) * 8;
    for (int nb = 0; nb < 4; nb++) {
        int n0 = nb * 64;
        wmma::fragment<wmma::accumulator, 16, 16, 16, float> acc[2][2];
#pragma unroll
        for (int i = 0; i < 2; i++)
#pragma unroll
            for (int j = 0; j < 2; j++) wmma::fill_fragment(acc[i][j], 0.f);

        for (int kc = 0; kc < 128; kc += 32) {
            {
                int r = tid >> 3, c = (tid & 7) * 8;
                *(uint4*)&Bs[r][c] = *(const uint4*)&g_hW3[(kc + r) * 256 + n0 + c];
            }
            __syncthreads();
#pragma unroll
            for (int ks = 0; ks < 2; ks++) {
                wmma::fragment<wmma::matrix_a, 16, 16, 16, __half, wmma::row_major> af[2];
                wmma::fragment<wmma::matrix_b, 16, 16, 16, __half, wmma::row_major> bf[2];
#pragma unroll
                for (int i = 0; i < 2; i++)
                    wmma::load_matrix_sync(af[i], &As[warp_m * 32 + i * 16][kc + ks * 16], 136);
#pragma unroll
                for (int j = 0; j < 2; j++)
                    wmma::load_matrix_sync(bf[j], &Bs[ks * 16][warp_n * 32 + j * 16], 72);
#pragma unroll
                for (int i = 0; i < 2; i++)
#pragma unroll
                    for (int j = 0; j < 2; j++)
                        wmma::mma_sync(acc[i][j], af[i], bf[j], acc[i][j]);
            }
            __syncthreads();
        }

        // epilogue: bias + relu + project against W45, accumulate into smem proj
#pragma unroll
        for (int i = 0; i < 2; i++) {
            float s0 = 0.f, s1 = 0.f, s2 = 0.f;
            int rl = warp_m * 32 + i * 16 + r_;
#pragma unroll
            for (int j = 0; j < 2; j++) {
                wmma::store_matrix_sync(&Es[wid][0], acc[i][j], 16, wmma::mem_row_major);
                __syncwarp();
                int gc = n0 + warp_n * 32 + j * 16 + cb;
#pragma unroll
                for (int t = 0; t < 8; t++) {
                    float f = Es[wid][r_ * 16 + cb + t] + bias[gc + t];
                    f = fmaxf(f, 0.f);
                    s0 += f * g_W45[(gc + t) * 3 + 0];
                    s1 += f * g_W45[(gc + t) * 3 + 1];
                    s2 += f * g_W45[(gc + t) * 3 + 2];
                }
                __syncwarp();
            }
            s0 += __shfl_xor_sync(0xffffffffu, s0, 1);
            s1 += __shfl_xor_sync(0xffffffffu, s1, 1);
            s2 += __shfl_xor_sync(0xffffffffu, s2, 1);
            if ((lane & 1) == 0) {
                atomicAdd(&proj[rl * 3 + 0], s0);
                atomicAdd(&proj[rl * 3 + 1], s1);
                atomicAdd(&proj[rl * 3 + 2], s2);
            }
        }
        __syncthreads();
    }

    for (int t = tid; t < 128; t += 256) {
        int node = row0 + t;
        if (node < N_NODES)
            g_proj[node] = make_float4(proj[t * 3 + 0], proj[t * 3 + 1], proj[t * 3 + 2], 0.f);
    }
}

// ---------------- final aggregation at D=3 over g_proj ----------------
__global__ void k_agg3(float* __restrict__ out) {
    int v = blockIdx.x * blockDim.x + threadIdx.x;
    if (v >= N_NODES) return;
    float selfn = g_dis[v];
    selfn *= selfn;
    float4 p = g_proj[v];
    float a0 = p.x * selfn, a1 = p.y * selfn, a2 = p.z * selfn;

    int s = g_rowptr[v];
    int e = s + g_cnt[v];
#pragma unroll 2
    for (int q = s; q < e; q++) {
        int src = __ldg(&g_col[q]);
        float w = __ldg(&g_val[q]);
        float4 h = __ldg(&g_proj[src]);
        a0 += h.x * w; a1 += h.y * w; a2 += h.z * w;
    }
    out[(size_t)v * 3 + 0] = a0 + g_b45[0];
    out[(size_t)v * 3 + 1] = a1 + g_b45[1];
    out[(size_t)v * 3 + 2] = a2 + g_b45[2];
}

// ---------------- launch ----------------
extern "C" void kernel_launch(void* const* d_in, const int* in_sizes, int n_in,
                              void* d_out, int out_size) {
    const float* x    = (const float*)d_in[0];
    const void*  ei   = d_in[1];
    const float* ew   = (const float*)d_in[2];
    const float* W1   = (const float*)d_in[3];
    const float* b1   = (const float*)d_in[4];
    const float* W2   = (const float*)d_in[5];
    const float* b2   = (const float*)d_in[6];
    const float* W3   = (const float*)d_in[7];
    const float* b3   = (const float*)d_in[8];
    const float* W4   = (const float*)d_in[9];
    const float* b4   = (const float*)d_in[10];
    const float* Wout = (const float*)d_in[11];
    const float* bout = (const float*)d_in[12];
    float* out = (float*)d_out;

    __half *hx, *hA, *hB, *hW1, *hW2, *hW3;
    cudaGetSymbolAddress((void**)&hx, g_hx);
    cudaGetSymbolAddress((void**)&hA, g_hA);
    cudaGetSymbolAddress((void**)&hB, g_hB);
    cudaGetSymbolAddress((void**)&hW1, g_hW1);
    cudaGetSymbolAddress((void**)&hW2, g_hW2);
    cudaGetSymbolAddress((void**)&hW3, g_hW3);

    static cudaStream_t s2 = nullptr;
    static cudaEvent_t evFork = nullptr, evJoin = nullptr, evJoin2 = nullptr;
    if (!s2) {
        cudaStreamCreateWithFlags(&s2, cudaStreamNonBlocking);
        cudaEventCreateWithFlags(&evFork, cudaEventDisableTiming);
        cudaEventCreateWithFlags(&evJoin, cudaEventDisableTiming);
        cudaEventCreateWithFlags(&evJoin2, cudaEventDisableTiming);
    }

    const int TB = 256;
    int nodeBlocks = (N_NODES + TB - 1) / TB;
    int edgeBlocks = (N_EDGES + TB - 1) / TB;
    int warpNodeBlocks = (N_NODES + 7) / 8;
    int gm = (N_NODES + 127) / 128;
    int cvtBlocks = ((NX + 49152) / 8 + TB - 1) / TB;

    // fork: conversions + GEMM1 needed at first agg; W45 fold before fused L3
    cudaEventRecord(evFork, 0);
    cudaStreamWaitEvent(s2, evFork, 0);
    k_cvtall<<<cvtBlocks, TB, 0, s2>>>(x, W1, W2, W3, hx, hW1, hW2, hW3);
    k_hgemm<<<dim3(gm, 1), 256, 0, s2>>>(hx, hW1, nullptr, hA, 128, 64, 0);
    cudaEventRecord(evJoin, s2);
    k_w45<<<97, 256, 0, s2>>>(W4, b4, Wout, bout);
    cudaEventRecord(evJoin2, s2);

    // main stream: CSR preprocessing (4 kernels)
    k_initdet<<<nodeBlocks, TB>>>((const long long*)ei);
    k_decdeg<<<edgeBlocks, TB>>>(ei, ew);
    k_disalloc<<<nodeBlocks, TB>>>();
    k_build<<<edgeBlocks, TB>>>(ei, ew);

    cudaStreamWaitEvent(0, evJoin, 0);

    // L1: h1 = relu(agg(t1) + b1)     hA(64) -> hB(64)
    k_agg64<true, true><<<warpNodeBlocks, 256>>>(hA, b1, hB);

    // L2 fused: t2 = relu(agg(h1) @ W2 + b2)      hB -> hA(128)
    k_agg_gemm2<<<gm, 256>>>(hB, b2, hA);

    // L3 fused: g_proj = relu(agg(t2) @ W3 + b3) @ W45     hA -> g_proj
    cudaStreamWaitEvent(0, evJoin2, 0);          // W45 ready
    k_agg_gemm3proj<<<gm, 256, 49152>>>(hA, b3);

    // L4 head: out = agg(g_proj) + b45
    k_agg3<<<nodeBlocks, TB>>>(out);

    (void)in_sizes; (void)n_in; (void)out_size;
}

// round 16
// speedup vs baseline: 1.2337x; 1.2337x over previous
#include <cuda_runtime.h>
#include <cuda_fp16.h>
#include <mma.h>

using namespace nvcuda;

#define N_NODES 100000
#define N_EDGES 1600000

typedef unsigned long long ull;

// ---------------- scratch (__device__ globals; no allocation allowed) ----------------
__device__ float g_deg[N_NODES];
__device__ float g_dis[N_NODES];
__device__ int   g_cnt[N_NODES];
__device__ int   g_rowptr[N_NODES];
__device__ int   g_fill[N_NODES];
__device__ ull   g_colval[N_EDGES];    // low32 = src, high32 = norm bits
__device__ int   g_is64;
__device__ int   g_total;
__device__ float g_W45[256 * 3];
__device__ float g_b45[3];
__device__ __half g_hx[(size_t)N_NODES * 128];
__device__ __half g_hA[(size_t)N_NODES * 256];
__device__ __half g_hB[(size_t)N_NODES * 256];
__device__ __half g_hW1[128 * 64];
__device__ __half g_hW2[64 * 128];
__device__ __half g_hW3[128 * 256];
__device__ float4 g_proj[N_NODES];

__device__ __forceinline__ void unpack_edge(ull pk, int& src, float& w) {
    src = (int)(unsigned)(pk & 0xffffffffu);
    w = __uint_as_float((unsigned)(pk >> 32));
}

// ---------------- fused init + dtype detection ----------------
__global__ void k_initdet(const long long* __restrict__ ei) {
    __shared__ int bigfound;
    int i = blockIdx.x * blockDim.x + threadIdx.x;
    if (i < N_NODES) {
        g_deg[i] = 1.0f;
        g_cnt[i] = 0;
    }
    if (blockIdx.x == 0) {
        if (threadIdx.x == 0) { bigfound = 0; g_total = 0; }
        __syncthreads();
        bool big = false;
#pragma unroll
        for (int j = 0; j < 8; j++) {
            ull v = (ull)ei[threadIdx.x * 8 + j];
            if (v >= (ull)N_NODES) big = true;
        }
        if (big) bigfound = 1;
        __syncthreads();
        if (threadIdx.x == 0) g_is64 = bigfound ? 0 : 1;
    }
}

__device__ __forceinline__ void decode_edge(const void* eiv, int e, int& s, int& d) {
    if (g_is64) {
        const long long* ei = (const long long*)eiv;
        s = (int)ei[e];
        d = (int)ei[N_EDGES + e];
    } else {
        const int* ei = (const int*)eiv;
        s = ei[e];
        d = ei[N_EDGES + e];
    }
}

__global__ void k_decdeg(const void* __restrict__ eiv, const float* __restrict__ ew) {
    int e = blockIdx.x * blockDim.x + threadIdx.x;
    if (e >= N_EDGES) return;
    int s, d;
    decode_edge(eiv, e, s, d);
    atomicAdd(&g_deg[d], ew[e]);
    atomicAdd(&g_cnt[d], 1);
}

// fused: dis = rsqrt(deg) AND CSR slot allocation (block scan + 1 atomic per block)
__global__ void k_disalloc() {
    __shared__ int s[256];
    __shared__ int sbase;
    int tid = threadIdx.x;
    int i = blockIdx.x * 256 + tid;
    int c = (i < N_NODES) ? g_cnt[i] : 0;
    if (i < N_NODES) g_dis[i] = rsqrtf(g_deg[i]);
    s[tid] = c;
    __syncthreads();
    for (int off = 1; off < 256; off <<= 1) {
        int t = (tid >= off) ? s[tid - off] : 0;
        __syncthreads();
        s[tid] += t;
        __syncthreads();
    }
    if (tid == 255) sbase = atomicAdd(&g_total, s[255]);
    __syncthreads();
    if (i < N_NODES) {
        int r = sbase + s[tid] - c;
        g_rowptr[i] = r;
        g_fill[i] = r;
    }
}

__global__ void k_build(const void* __restrict__ eiv, const float* __restrict__ ew) {
    int e = blockIdx.x * blockDim.x + threadIdx.x;
    if (e >= N_EDGES) return;
    int s, d;
    decode_edge(eiv, e, s, d);
    float nm = g_dis[s] * ew[e] * g_dis[d];
    int p = atomicAdd(&g_fill[d], 1);
    g_colval[p] = ((ull)__float_as_uint(nm) << 32) | (unsigned)s;
}

// parallel fold: W45[k][c] = sum_j W4[k][j] * Wout[j][c]; one warp per output
__global__ void k_w45(const float* __restrict__ W4, const float* __restrict__ b4,
                      const float* __restrict__ Wout, const float* __restrict__ bout) {
    int gw = (blockIdx.x * blockDim.x + threadIdx.x) >> 5;
    int lane = threadIdx.x & 31;
    if (gw < 768) {
        int k = gw / 3, c = gw % 3;
        float s = 0.f;
#pragma unroll
        for (int j = lane; j < 256; j += 32)
            s += W4[k * 256 + j] * Wout[j * 3 + c];
#pragma unroll
        for (int off = 16; off; off >>= 1)
            s += __shfl_down_sync(0xffffffffu, s, off);
        if (lane == 0) g_W45[gw] = s;
    } else if (gw < 771) {
        int c = gw - 768;
        float s = 0.f;
#pragma unroll
        for (int j = lane; j < 256; j += 32)
            s += b4[j] * Wout[j * 3 + c];
#pragma unroll
        for (int off = 16; off; off >>= 1)
            s += __shfl_down_sync(0xffffffffu, s, off);
        if (lane == 0) g_b45[c] = s + bout[c];
    }
}

// ---------------- fused fp32->fp16: x (12.8M) then W1/W2/W3 (49152) ----------------
#define NX (N_NODES * 128)
__global__ void k_cvtall(const float* __restrict__ x, const float* __restrict__ W1,
                         const float* __restrict__ W2, const float* __restrict__ W3,
                         __half* __restrict__ hx, __half* __restrict__ h1,
                         __half* __restrict__ h2, __half* __restrict__ h3) {
    int i = (blockIdx.x * blockDim.x + threadIdx.x) * 8;
    const float* in;
    __half* out;
    if (i < NX) { in = x; out = hx; }
    else {
        int w = i - NX;
        if (w < 8192) { in = W1; out = h1; i = w; }
        else if (w < 16384) { in = W2; out = h2; i = w - 8192; }
        else if (w < 49152) { in = W3; out = h3; i = w - 16384; }
        else return;
    }
    float4 a = *(const float4*)&in[i];
    float4 b = *(const float4*)&in[i + 4];
    __half2 q0 = __floats2half2_rn(a.x, a.y);
    __half2 q1 = __floats2half2_rn(a.z, a.w);
    __half2 q2 = __floats2half2_rn(b.x, b.y);
    __half2 q3 = __floats2half2_rn(b.z, b.w);
    uint4 pk;
    pk.x = *(unsigned*)&q0; pk.y = *(unsigned*)&q1;
    pk.z = *(unsigned*)&q2; pk.w = *(unsigned*)&q3;
    *(uint4*)&out[i] = pk;
}

// ---------------- HMMA GEMM (wmma): double-buffered, BK=32, fp16 output ----------------
__global__ void k_hgemm(const __half* __restrict__ A, const __half* __restrict__ W,
                        const float* __restrict__ bias, __half* __restrict__ C,
                        int din, int dout, int relu) {
    __shared__ __half As[2][128][40];
    __shared__ __half Bs[2][32][72];
    __shared__ float Es[8][256];

    int tid = threadIdx.x;
    int lane = tid & 31;
    int wid = tid >> 5;
    int warp_m = wid & 3;
    int warp_n = wid >> 2;
    int row0 = blockIdx.x * 128;
    int col0 = blockIdx.y * 64;

    int ar0 = tid >> 1, ac0 = (tid & 1) * 8;
    int br = tid >> 3, bc = (tid & 7) * 8;

    wmma::fragment<wmma::accumulator, 16, 16, 16, float> acc[2][2];
#pragma unroll
    for (int i = 0; i < 2; i++)
#pragma unroll
        for (int j = 0; j < 2; j++) wmma::fill_fragment(acc[i][j], 0.f);

    int nk = din >> 5;

    {
        uint4 v0 = make_uint4(0, 0, 0, 0), v1 = v0;
        if (row0 + ar0 < N_NODES) {
            v0 = *(const uint4*)&A[(size_t)(row0 + ar0) * din + ac0];
            v1 = *(const uint4*)&A[(size_t)(row0 + ar0) * din + ac0 + 16];
        }
        *(uint4*)&As[0][ar0][ac0] = v0;
        *(uint4*)&As[0][ar0][ac0 + 16] = v1;
        *(uint4*)&Bs[0][br][bc] = *(const uint4*)&W[(size_t)br * dout + col0 + bc];
    }
    __syncthreads();

    for (int kt = 0; kt < nk; kt++) {
        int cur = kt & 1;
        bool more = (kt + 1 < nk);
        uint4 p0, p1, pb;
        if (more) {
            int k0 = (kt + 1) << 5;
            p0 = make_uint4(0, 0, 0, 0); p1 = p0;
            if (row0 + ar0 < N_NODES) {
                p0 = *(const uint4*)&A[(size_t)(row0 + ar0) * din + k0 + ac0];
                p1 = *(const uint4*)&A[(size_t)(row0 + ar0) * din + k0 + ac0 + 16];
            }
            pb = *(const uint4*)&W[(size_t)(k0 + br) * dout + col0 + bc];
        }
#pragma unroll
        for (int ks = 0; ks < 2; ks++) {
            wmma::fragment<wmma::matrix_a, 16, 16, 16, __half, wmma::row_major> af[2];
            wmma::fragment<wmma::matrix_b, 16, 16, 16, __half, wmma::row_major> bf[2];
#pragma unroll
            for (int i = 0; i < 2; i++)
                wmma::load_matrix_sync(af[i], &As[cur][warp_m * 32 + i * 16][ks * 16], 40);
#pragma unroll
            for (int j = 0; j < 2; j++)
                wmma::load_matrix_sync(bf[j], &Bs[cur][ks * 16][warp_n * 32 + j * 16], 72);
#pragma unroll
            for (int i = 0; i < 2; i++)
#pragma unroll
                for (int j = 0; j < 2; j++)
                    wmma::mma_sync(acc[i][j], af[i], bf[j], acc[i][j]);
        }
        if (more) {
            int nxt = cur ^ 1;
            *(uint4*)&As[nxt][ar0][ac0] = p0;
            *(uint4*)&As[nxt][ar0][ac0 + 16] = p1;
            *(uint4*)&Bs[nxt][br][bc] = pb;
            __syncthreads();
        }
    }

#pragma unroll
    for (int i = 0; i < 2; i++) {
#pragma unroll
        for (int j = 0; j < 2; j++) {
            wmma::store_matrix_sync(&Es[wid][0], acc[i][j], 16, wmma::mem_row_major);
            __syncwarp();
            int r = lane >> 1, c = (lane & 1) * 8;
            int gr = row0 + warp_m * 32 + i * 16 + r;
            int gc = col0 + warp_n * 32 + j * 16 + c;
            if (gr < N_NODES) {
                float v[8];
#pragma unroll
                for (int t = 0; t < 8; t++) {
                    float f = Es[wid][r * 16 + c + t];
                    if (bias) f += bias[gc + t];
                    if (relu) f = fmaxf(f, 0.f);
                    v[t] = f;
                }
                __half2 h0 = __floats2half2_rn(v[0], v[1]);
                __half2 h1 = __floats2half2_rn(v[2], v[3]);
                __half2 h2 = __floats2half2_rn(v[4], v[5]);
                __half2 h3 = __floats2half2_rn(v[6], v[7]);
                uint4 pk;
                pk.x = *(unsigned*)&h0; pk.y = *(unsigned*)&h1;
                pk.z = *(unsigned*)&h2; pk.w = *(unsigned*)&h3;
                *(uint4*)&C[(size_t)gr * dout + gc] = pk;
            }
            __syncwarp();
        }
    }
}

// ---------------- GEMM3 + projection, single block per row tile, no global atomics ----------------
// A tile (128x128) loaded ONCE into smem; loops 4 x 64-col slabs of W3;
// projection accumulated in registers, combined in smem (Es reused), plain store.
__global__ void k_hgemm_proj(const __half* __restrict__ A, const float* __restrict__ bias) {
    __shared__ __half As[128][136];   // 34816 B
    __shared__ __half Bs[32][72];     // 4608 B
    __shared__ float Es[8][256];      // 8192 B  (reused as proj buffer at the end)

    int tid = threadIdx.x;
    int lane = tid & 31;
    int wid = tid >> 5;
    int warp_m = wid & 3;
    int warp_n = wid >> 2;
    int row0 = blockIdx.x * 128;

    // load A tile once: 128 rows x 128 halves = 2048 uint4
    for (int idx = tid; idx < 2048; idx += 256) {
        int r = idx >> 4, c = (idx & 15) * 8;
        uint4 v = make_uint4(0, 0, 0, 0);
        if (row0 + r < N_NODES) v = *(const uint4*)&A[(size_t)(row0 + r) * 128 + c];
        *(uint4*)&As[r][c] = v;
    }
    __syncthreads();

    int r_ = lane >> 1, cb = (lane & 1) * 8;
    float sacc[2][3];
#pragma unroll
    for (int i = 0; i < 2; i++) { sacc[i][0] = 0.f; sacc[i][1] = 0.f; sacc[i][2] = 0.f; }

    for (int nb = 0; nb < 4; nb++) {
        int n0 = nb * 64;
        wmma::fragment<wmma::accumulator, 16, 16, 16, float> acc[2][2];
#pragma unroll
        for (int i = 0; i < 2; i++)
#pragma unroll
            for (int j = 0; j < 2; j++) wmma::fill_fragment(acc[i][j], 0.f);

        for (int kc = 0; kc < 128; kc += 32) {
            {
                int r = tid >> 3, c = (tid & 7) * 8;
                *(uint4*)&Bs[r][c] = *(const uint4*)&g_hW3[(kc + r) * 256 + n0 + c];
            }
            __syncthreads();
#pragma unroll
            for (int ks = 0; ks < 2; ks++) {
                wmma::fragment<wmma::matrix_a, 16, 16, 16, __half, wmma::row_major> af[2];
                wmma::fragment<wmma::matrix_b, 16, 16, 16, __half, wmma::row_major> bf[2];
#pragma unroll
                for (int i = 0; i < 2; i++)
                    wmma::load_matrix_sync(af[i], &As[warp_m * 32 + i * 16][kc + ks * 16], 136);
#pragma unroll
                for (int j = 0; j < 2; j++)
                    wmma::load_matrix_sync(bf[j], &Bs[ks * 16][warp_n * 32 + j * 16], 72);
#pragma unroll
                for (int i = 0; i < 2; i++)
#pragma unroll
                    for (int j = 0; j < 2; j++)
                        wmma::mma_sync(acc[i][j], af[i], bf[j], acc[i][j]);
            }
            __syncthreads();
        }

        // bias + relu + project against W45, accumulate in registers
#pragma unroll
        for (int i = 0; i < 2; i++) {
#pragma unroll
            for (int j = 0; j < 2; j++) {
                wmma::store_matrix_sync(&Es[wid][0], acc[i][j], 16, wmma::mem_row_major);
                __syncwarp();
                int gc = n0 + warp_n * 32 + j * 16 + cb;
#pragma unroll
                for (int t = 0; t < 8; t++) {
                    float f = Es[wid][r_ * 16 + cb + t] + bias[gc + t];
                    f = fmaxf(f, 0.f);
                    sacc[i][0] += f * g_W45[(gc + t) * 3 + 0];
                    sacc[i][1] += f * g_W45[(gc + t) * 3 + 1];
                    sacc[i][2] += f * g_W45[(gc + t) * 3 + 2];
                }
                __syncwarp();
            }
        }
    }

    // combine lane pairs + across warp_n in smem (Es reused), then plain store
    float* proj = (float*)Es;   // 128*3 floats
    __syncthreads();
    for (int t = tid; t < 384; t += 256) proj[t] = 0.f;
    __syncthreads();
#pragma unroll
    for (int i = 0; i < 2; i++) {
        float s0 = sacc[i][0], s1 = sacc[i][1], s2 = sacc[i][2];
        s0 += __shfl_xor_sync(0xffffffffu, s0, 1);
        s1 += __shfl_xor_sync(0xffffffffu, s1, 1);
        s2 += __shfl_xor_sync(0xffffffffu, s2, 1);
        if ((lane & 1) == 0) {
            int rl = warp_m * 32 + i * 16 + r_;
            atomicAdd(&proj[rl * 3 + 0], s0);
            atomicAdd(&proj[rl * 3 + 1], s1);
            atomicAdd(&proj[rl * 3 + 2], s2);
        }
    }
    __syncthreads();
    for (int t = tid; t < 128; t += 256) {
        int node = row0 + t;
        if (node < N_NODES)
            g_proj[node] = make_float4(proj[t * 3 + 0], proj[t * 3 + 1], proj[t * 3 + 2], 0.f);
    }
}

// ---------------- aggregation D=64 fp16: 4 edges per warp (8 lanes x 16B each) ----------------
template <bool BIAS, bool RELU>
__global__ void k_agg64(const __half* __restrict__ H, const float* __restrict__ bias,
                        __half* __restrict__ out) {
    int warp = (blockIdx.x * blockDim.x + threadIdx.x) >> 5;
    int lane = threadIdx.x & 31;
    if (warp >= N_NODES) return;
    int grp = lane >> 3, gl = lane & 7;
    const uint4* H4 = (const uint4*)H;

    float a[8];
#pragma unroll
    for (int j = 0; j < 8; j++) a[j] = 0.f;

    if (grp == 0) {
        float selfn = g_dis[warp];
        selfn *= selfn;
        uint4 v = H4[(size_t)warp * 8 + gl];
        const __half2* h2 = (const __half2*)&v;
#pragma unroll
        for (int j = 0; j < 4; j++) {
            float2 f = __half22float2(h2[j]);
            a[2 * j] = f.x * selfn;
            a[2 * j + 1] = f.y * selfn;
        }
    }

    int s = g_rowptr[warp];
    int e = s + g_cnt[warp];
    for (int p = s + grp; p < e; p += 4) {
        int src; float w;
        unpack_edge(__ldg(&g_colval[p]), src, w);
        uint4 v = __ldg(&H4[(size_t)src * 8 + gl]);
        const __half2* h2 = (const __half2*)&v;
#pragma unroll
        for (int j = 0; j < 4; j++) {
            float2 f = __half22float2(h2[j]);
            a[2 * j] += f.x * w;
            a[2 * j + 1] += f.y * w;
        }
    }
    __syncwarp();
#pragma unroll
    for (int j = 0; j < 8; j++) {
        a[j] += __shfl_xor_sync(0xffffffffu, a[j], 8);
        a[j] += __shfl_xor_sync(0xffffffffu, a[j], 16);
    }
    if (grp == 0) {
#pragma unroll
        for (int j = 0; j < 8; j++) {
            if (BIAS) a[j] += bias[gl * 8 + j];
            if (RELU) a[j] = fmaxf(a[j], 0.f);
        }
        __half2 h0 = __floats2half2_rn(a[0], a[1]);
        __half2 h1 = __floats2half2_rn(a[2], a[3]);
        __half2 h2o = __floats2half2_rn(a[4], a[5]);
        __half2 h3 = __floats2half2_rn(a[6], a[7]);
        uint4 pk;
        pk.x = *(unsigned*)&h0; pk.y = *(unsigned*)&h1;
        pk.z = *(unsigned*)&h2o; pk.w = *(unsigned*)&h3;
        ((uint4*)out)[(size_t)warp * 8 + gl] = pk;
    }
}

// ---------------- aggregation D=128 fp16 in/out: 2 edges per warp (16 lanes x 16B) ----------------
__global__ void k_agg128(const __half* __restrict__ H, __half* __restrict__ out) {
    int warp = (blockIdx.x * blockDim.x + threadIdx.x) >> 5;
    int lane = threadIdx.x & 31;
    if (warp >= N_NODES) return;
    int half = lane >> 4, hl = lane & 15;
    const uint4* H4 = (const uint4*)H;

    float a[8];
#pragma unroll
    for (int j = 0; j < 8; j++) a[j] = 0.f;

    if (half == 0) {
        float selfn = g_dis[warp];
        selfn *= selfn;
        uint4 v = H4[(size_t)warp * 16 + hl];
        const __half2* h2 = (const __half2*)&v;
#pragma unroll
        for (int j = 0; j < 4; j++) {
            float2 f = __half22float2(h2[j]);
            a[2 * j] = f.x * selfn;
            a[2 * j + 1] = f.y * selfn;
        }
    }

    int s = g_rowptr[warp];
    int e = s + g_cnt[warp];
    for (int p = s + half; p < e; p += 2) {
        int src; float w;
        unpack_edge(__ldg(&g_colval[p]), src, w);
        uint4 v = __ldg(&H4[(size_t)src * 16 + hl]);
        const __half2* h2 = (const __half2*)&v;
#pragma unroll
        for (int j = 0; j < 4; j++) {
            float2 f = __half22float2(h2[j]);
            a[2 * j] += f.x * w;
            a[2 * j + 1] += f.y * w;
        }
    }
    __syncwarp();
#pragma unroll
    for (int j = 0; j < 8; j++)
        a[j] += __shfl_xor_sync(0xffffffffu, a[j], 16);
    if (half == 0) {
        __half2 h0 = __floats2half2_rn(a[0], a[1]);
        __half2 h1 = __floats2half2_rn(a[2], a[3]);
        __half2 h2o = __floats2half2_rn(a[4], a[5]);
        __half2 h3 = __floats2half2_rn(a[6], a[7]);
        uint4 pk;
        pk.x = *(unsigned*)&h0; pk.y = *(unsigned*)&h1;
        pk.z = *(unsigned*)&h2o; pk.w = *(unsigned*)&h3;
        ((uint4*)out)[(size_t)warp * 16 + hl] = pk;
    }
}

// ---------------- final aggregation at D=3 over g_proj ----------------
__global__ void k_agg3(float* __restrict__ out) {
    int v = blockIdx.x * blockDim.x + threadIdx.x;
    if (v >= N_NODES) return;
    float selfn = g_dis[v];
    selfn *= selfn;
    float4 p = g_proj[v];
    float a0 = p.x * selfn, a1 = p.y * selfn, a2 = p.z * selfn;

    int s = g_rowptr[v];
    int e = s + g_cnt[v];
#pragma unroll 2
    for (int q = s; q < e; q++) {
        int src; float w;
        unpack_edge(__ldg(&g_colval[q]), src, w);
        float4 h = __ldg(&g_proj[src]);
        a0 += h.x * w; a1 += h.y * w; a2 += h.z * w;
    }
    out[(size_t)v * 3 + 0] = a0 + g_b45[0];
    out[(size_t)v * 3 + 1] = a1 + g_b45[1];
    out[(size_t)v * 3 + 2] = a2 + g_b45[2];
}

// ---------------- launch ----------------
extern "C" void kernel_launch(void* const* d_in, const int* in_sizes, int n_in,
                              void* d_out, int out_size) {
    const float* x    = (const float*)d_in[0];
    const void*  ei   = d_in[1];
    const float* ew   = (const float*)d_in[2];
    const float* W1   = (const float*)d_in[3];
    const float* b1   = (const float*)d_in[4];
    const float* W2   = (const float*)d_in[5];
    const float* b2   = (const float*)d_in[6];
    const float* W3   = (const float*)d_in[7];
    const float* b3   = (const float*)d_in[8];
    const float* W4   = (const float*)d_in[9];
    const float* b4   = (const float*)d_in[10];
    const float* Wout = (const float*)d_in[11];
    const float* bout = (const float*)d_in[12];
    float* out = (float*)d_out;

    __half *hx, *hA, *hB, *hW1, *hW2, *hW3;
    cudaGetSymbolAddress((void**)&hx, g_hx);
    cudaGetSymbolAddress((void**)&hA, g_hA);
    cudaGetSymbolAddress((void**)&hB, g_hB);
    cudaGetSymbolAddress((void**)&hW1, g_hW1);
    cudaGetSymbolAddress((void**)&hW2, g_hW2);
    cudaGetSymbolAddress((void**)&hW3, g_hW3);

    static cudaStream_t s2 = nullptr;
    static cudaEvent_t evFork = nullptr, evJoin = nullptr, evJoin2 = nullptr;
    if (!s2) {
        cudaStreamCreateWithFlags(&s2, cudaStreamNonBlocking);
        cudaEventCreateWithFlags(&evFork, cudaEventDisableTiming);
        cudaEventCreateWithFlags(&evJoin, cudaEventDisableTiming);
        cudaEventCreateWithFlags(&evJoin2, cudaEventDisableTiming);
    }

    const int TB = 256;
    int nodeBlocks = (N_NODES + TB - 1) / TB;
    int edgeBlocks = (N_EDGES + TB - 1) / TB;
    int warpNodeBlocks = (N_NODES + 7) / 8;
    int gm = (N_NODES + 127) / 128;
    int cvtBlocks = ((NX + 49152) / 8 + TB - 1) / TB;

    // fork: conversions + GEMM1 needed at first agg; W45 fold before fused L3
    cudaEventRecord(evFork, 0);
    cudaStreamWaitEvent(s2, evFork, 0);
    k_cvtall<<<cvtBlocks, TB, 0, s2>>>(x, W1, W2, W3, hx, hW1, hW2, hW3);
    k_hgemm<<<dim3(gm, 1), 256, 0, s2>>>(hx, hW1, nullptr, hA, 128, 64, 0);
    cudaEventRecord(evJoin, s2);
    k_w45<<<97, 256, 0, s2>>>(W4, b4, Wout, bout);
    cudaEventRecord(evJoin2, s2);

    // main stream: CSR preprocessing (4 kernels)
    k_initdet<<<nodeBlocks, TB>>>((const long long*)ei);
    k_decdeg<<<edgeBlocks, TB>>>(ei, ew);
    k_disalloc<<<nodeBlocks, TB>>>();
    k_build<<<edgeBlocks, TB>>>(ei, ew);

    cudaStreamWaitEvent(0, evJoin, 0);

    // L1: h1 = relu(agg(t1) + b1)
    k_agg64<true, true><<<warpNodeBlocks, 256>>>(hA, b1, hB);

    // L2: h2 = relu(agg(h1) @ W2 + b2)
    k_agg64<false, false><<<warpNodeBlocks, 256>>>(hB, nullptr, hA);
    k_hgemm<<<dim3(gm, 2), 256>>>(hA, hW2, b2, hB, 64, 128, 1);

    // L3 + proj fused: g_proj = relu(agg(h2) @ W3 + b3) @ W45   (h3 never materialized)
    k_agg128<<<warpNodeBlocks, 256>>>(hB, hA);
    cudaStreamWaitEvent(0, evJoin2, 0);          // W45 ready
    k_hgemm_proj<<<gm, 256>>>(hA, b3);

    // L4 head: out = agg(g_proj) + b45
    k_agg3<<<nodeBlocks, TB>>>(out);

    (void)in_sizes; (void)n_in; (void)out_size;
}

// round 17
// speedup vs baseline: 1.2779x; 1.0359x over previous
#include <cuda_runtime.h>
#include <cuda_fp16.h>
#include <mma.h>

using namespace nvcuda;

#define N_NODES 100000
#define N_EDGES 1600000

typedef unsigned long long ull;

// ---------------- scratch (__device__ globals; no allocation allowed) ----------------
__device__ float g_deg[N_NODES];
__device__ float g_dis[N_NODES];
__device__ int   g_cnt[N_NODES];
__device__ ull   g_rowcnt[N_NODES];    // (cnt << 32) | rowptr
__device__ int   g_fill[N_NODES];
__device__ ull   g_colval[N_EDGES];    // low32 = src, high32 = norm bits
__device__ int   g_is64;
__device__ int   g_total;
__device__ float g_W45[256 * 3];
__device__ float g_b45[3];
__device__ __half g_hA[(size_t)N_NODES * 256];
__device__ __half g_hB[(size_t)N_NODES * 256];
__device__ __half g_hW1[128 * 64];
__device__ __half g_hW2[64 * 128];
__device__ __half g_hW3[128 * 256];
__device__ float4 g_proj[N_NODES];

__device__ __forceinline__ void unpack_edge(ull pk, int& src, float& w) {
    src = (int)(unsigned)(pk & 0xffffffffu);
    w = __uint_as_float((unsigned)(pk >> 32));
}
__device__ __forceinline__ void unpack_row(ull pk, int& s, int& e) {
    s = (int)(unsigned)(pk & 0xffffffffu);
    e = s + (int)(unsigned)(pk >> 32);
}

// ---------------- fused init + dtype detection ----------------
__global__ void k_initdet(const long long* __restrict__ ei) {
    __shared__ int bigfound;
    int i = blockIdx.x * blockDim.x + threadIdx.x;
    if (i < N_NODES) {
        g_deg[i] = 1.0f;
        g_cnt[i] = 0;
    }
    if (blockIdx.x == 0) {
        if (threadIdx.x == 0) { bigfound = 0; g_total = 0; }
        __syncthreads();
        bool big = false;
#pragma unroll
        for (int j = 0; j < 8; j++) {
            ull v = (ull)ei[threadIdx.x * 8 + j];
            if (v >= (ull)N_NODES) big = true;
        }
        if (big) bigfound = 1;
        __syncthreads();
        if (threadIdx.x == 0) g_is64 = bigfound ? 0 : 1;
    }
}

__device__ __forceinline__ void decode_edge(const void* eiv, int e, int& s, int& d) {
    if (g_is64) {
        const long long* ei = (const long long*)eiv;
        s = (int)ei[e];
        d = (int)ei[N_EDGES + e];
    } else {
        const int* ei = (const int*)eiv;
        s = ei[e];
        d = ei[N_EDGES + e];
    }
}

__global__ void k_decdeg(const void* __restrict__ eiv, const float* __restrict__ ew) {
    int e = blockIdx.x * blockDim.x + threadIdx.x;
    if (e >= N_EDGES) return;
    int s, d;
    decode_edge(eiv, e, s, d);
    atomicAdd(&g_deg[d], ew[e]);
    atomicAdd(&g_cnt[d], 1);
}

// fused: dis = rsqrt(deg) AND CSR slot allocation (block scan + 1 atomic per block)
__global__ void k_disalloc() {
    __shared__ int s[256];
    __shared__ int sbase;
    int tid = threadIdx.x;
    int i = blockIdx.x * 256 + tid;
    int c = (i < N_NODES) ? g_cnt[i] : 0;
    if (i < N_NODES) g_dis[i] = rsqrtf(g_deg[i]);
    s[tid] = c;
    __syncthreads();
    for (int off = 1; off < 256; off <<= 1) {
        int t = (tid >= off) ? s[tid - off] : 0;
        __syncthreads();
        s[tid] += t;
        __syncthreads();
    }
    if (tid == 255) sbase = atomicAdd(&g_total, s[255]);
    __syncthreads();
    if (i < N_NODES) {
        int r = sbase + s[tid] - c;
        g_rowcnt[i] = ((ull)(unsigned)c << 32) | (unsigned)r;
        g_fill[i] = r;
    }
}

__global__ void k_build(const void* __restrict__ eiv, const float* __restrict__ ew) {
    int e = blockIdx.x * blockDim.x + threadIdx.x;
    if (e >= N_EDGES) return;
    int s, d;
    decode_edge(eiv, e, s, d);
    float nm = g_dis[s] * ew[e] * g_dis[d];
    int p = atomicAdd(&g_fill[d], 1);
    g_colval[p] = ((ull)__float_as_uint(nm) << 32) | (unsigned)s;
}

// parallel fold: W45[k][c] = sum_j W4[k][j] * Wout[j][c]; one warp per output
__global__ void k_w45(const float* __restrict__ W4, const float* __restrict__ b4,
                      const float* __restrict__ Wout, const float* __restrict__ bout) {
    int gw = (blockIdx.x * blockDim.x + threadIdx.x) >> 5;
    int lane = threadIdx.x & 31;
    if (gw < 768) {
        int k = gw / 3, c = gw % 3;
        float s = 0.f;
#pragma unroll
        for (int j = lane; j < 256; j += 32)
            s += W4[k * 256 + j] * Wout[j * 3 + c];
#pragma unroll
        for (int off = 16; off; off >>= 1)
            s += __shfl_down_sync(0xffffffffu, s, off);
        if (lane == 0) g_W45[gw] = s;
    } else if (gw < 771) {
        int c = gw - 768;
        float s = 0.f;
#pragma unroll
        for (int j = lane; j < 256; j += 32)
            s += b4[j] * Wout[j * 3 + c];
#pragma unroll
        for (int off = 16; off; off >>= 1)
            s += __shfl_down_sync(0xffffffffu, s, off);
        if (lane == 0) g_b45[c] = s + bout[c];
    }
}

// ---------------- fp32->fp16 for the three weight matrices only (49152 elems) ----------------
__global__ void k_cvtw(const float* __restrict__ W1, const float* __restrict__ W2,
                       const float* __restrict__ W3, __half* __restrict__ h1,
                       __half* __restrict__ h2, __half* __restrict__ h3) {
    int i = (blockIdx.x * blockDim.x + threadIdx.x) * 8;
    const float* in;
    __half* out;
    if (i < 8192) { in = W1; out = h1; }
    else if (i < 16384) { in = W2; out = h2; i -= 8192; }
    else if (i < 49152) { in = W3; out = h3; i -= 16384; }
    else return;
    float4 a = *(const float4*)&in[i];
    float4 b = *(const float4*)&in[i + 4];
    __half2 q0 = __floats2half2_rn(a.x, a.y);
    __half2 q1 = __floats2half2_rn(a.z, a.w);
    __half2 q2 = __floats2half2_rn(b.x, b.y);
    __half2 q3 = __floats2half2_rn(b.z, b.w);
    uint4 pk;
    pk.x = *(unsigned*)&q0; pk.y = *(unsigned*)&q1;
    pk.z = *(unsigned*)&q2; pk.w = *(unsigned*)&q3;
    *(uint4*)&out[i] = pk;
}

// load 8 contiguous halves worth of A data, converting from fp32 if needed
__device__ __forceinline__ uint4 ld8h_f32(const float* p) {
    float4 a = *(const float4*)p;
    float4 b = *(const float4*)(p + 4);
    __half2 q0 = __floats2half2_rn(a.x, a.y);
    __half2 q1 = __floats2half2_rn(a.z, a.w);
    __half2 q2 = __floats2half2_rn(b.x, b.y);
    __half2 q3 = __floats2half2_rn(b.z, b.w);
    uint4 pk;
    pk.x = *(unsigned*)&q0; pk.y = *(unsigned*)&q1;
    pk.z = *(unsigned*)&q2; pk.w = *(unsigned*)&q3;
    return pk;
}

// ---------------- HMMA GEMM (wmma): double-buffered, BK=32, fp16 output ----------------
// AIN32: A operand is fp32 in gmem (converted during tile load)
template <bool AIN32>
__global__ void k_hgemm(const void* __restrict__ Av, const __half* __restrict__ W,
                        const float* __restrict__ bias, __half* __restrict__ C,
                        int din, int dout, int relu) {
    __shared__ __half As[2][128][40];
    __shared__ __half Bs[2][32][72];
    __shared__ float Es[8][256];

    int tid = threadIdx.x;
    int lane = tid & 31;
    int wid = tid >> 5;
    int warp_m = wid & 3;
    int warp_n = wid >> 2;
    int row0 = blockIdx.x * 128;
    int col0 = blockIdx.y * 64;

    int ar0 = tid >> 1, ac0 = (tid & 1) * 8;
    int br = tid >> 3, bc = (tid & 7) * 8;

    const __half* Ah = (const __half*)Av;
    const float* Af = (const float*)Av;

    wmma::fragment<wmma::accumulator, 16, 16, 16, float> acc[2][2];
#pragma unroll
    for (int i = 0; i < 2; i++)
#pragma unroll
        for (int j = 0; j < 2; j++) wmma::fill_fragment(acc[i][j], 0.f);

    int nk = din >> 5;

    {
        uint4 v0 = make_uint4(0, 0, 0, 0), v1 = v0;
        if (row0 + ar0 < N_NODES) {
            if (AIN32) {
                v0 = ld8h_f32(&Af[(size_t)(row0 + ar0) * din + ac0]);
                v1 = ld8h_f32(&Af[(size_t)(row0 + ar0) * din + ac0 + 16]);
            } else {
                v0 = *(const uint4*)&Ah[(size_t)(row0 + ar0) * din + ac0];
                v1 = *(const uint4*)&Ah[(size_t)(row0 + ar0) * din + ac0 + 16];
            }
        }
        *(uint4*)&As[0][ar0][ac0] = v0;
        *(uint4*)&As[0][ar0][ac0 + 16] = v1;
        *(uint4*)&Bs[0][br][bc] = *(const uint4*)&W[(size_t)br * dout + col0 + bc];
    }
    __syncthreads();

    for (int kt = 0; kt < nk; kt++) {
        int cur = kt & 1;
        bool more = (kt + 1 < nk);
        uint4 p0, p1, pb;
        if (more) {
            int k0 = (kt + 1) << 5;
            p0 = make_uint4(0, 0, 0, 0); p1 = p0;
            if (row0 + ar0 < N_NODES) {
                if (AIN32) {
                    p0 = ld8h_f32(&Af[(size_t)(row0 + ar0) * din + k0 + ac0]);
                    p1 = ld8h_f32(&Af[(size_t)(row0 + ar0) * din + k0 + ac0 + 16]);
                } else {
                    p0 = *(const uint4*)&Ah[(size_t)(row0 + ar0) * din + k0 + ac0];
                    p1 = *(const uint4*)&Ah[(size_t)(row0 + ar0) * din + k0 + ac0 + 16];
                }
            }
            pb = *(const uint4*)&W[(size_t)(k0 + br) * dout + col0 + bc];
        }
#pragma unroll
        for (int ks = 0; ks < 2; ks++) {
            wmma::fragment<wmma::matrix_a, 16, 16, 16, __half, wmma::row_major> af[2];
            wmma::fragment<wmma::matrix_b, 16, 16, 16, __half, wmma::row_major> bf[2];
#pragma unroll
            for (int i = 0; i < 2; i++)
                wmma::load_matrix_sync(af[i], &As[cur][warp_m * 32 + i * 16][ks * 16], 40);
#pragma unroll
            for (int j = 0; j < 2; j++)
                wmma::load_matrix_sync(bf[j], &Bs[cur][ks * 16][warp_n * 32 + j * 16], 72);
#pragma unroll
            for (int i = 0; i < 2; i++)
#pragma unroll
                for (int j = 0; j < 2; j++)
                    wmma::mma_sync(acc[i][j], af[i], bf[j], acc[i][j]);
        }
        if (more) {
            int nxt = cur ^ 1;
            *(uint4*)&As[nxt][ar0][ac0] = p0;
            *(uint4*)&As[nxt][ar0][ac0 + 16] = p1;
            *(uint4*)&Bs[nxt][br][bc] = pb;
            __syncthreads();
        }
    }

#pragma unroll
    for (int i = 0; i < 2; i++) {
#pragma unroll
        for (int j = 0; j < 2; j++) {
            wmma::store_matrix_sync(&Es[wid][0], acc[i][j], 16, wmma::mem_row_major);
            __syncwarp();
            int r = lane >> 1, c = (lane & 1) * 8;
            int gr = row0 + warp_m * 32 + i * 16 + r;
            int gc = col0 + warp_n * 32 + j * 16 + c;
            if (gr < N_NODES) {
                float v[8];
#pragma unroll
                for (int t = 0; t < 8; t++) {
                    float f = Es[wid][r * 16 + c + t];
                    if (bias) f += bias[gc + t];
                    if (relu) f = fmaxf(f, 0.f);
                    v[t] = f;
                }
                __half2 h0 = __floats2half2_rn(v[0], v[1]);
                __half2 h1 = __floats2half2_rn(v[2], v[3]);
                __half2 h2 = __floats2half2_rn(v[4], v[5]);
                __half2 h3 = __floats2half2_rn(v[6], v[7]);
                uint4 pk;
                pk.x = *(unsigned*)&h0; pk.y = *(unsigned*)&h1;
                pk.z = *(unsigned*)&h2; pk.w = *(unsigned*)&h3;
                *(uint4*)&C[(size_t)gr * dout + gc] = pk;
            }
            __syncwarp();
        }
    }
}

// ---------------- GEMM3 + projection, single block per row tile, no global atomics ----------------
__global__ void k_hgemm_proj(const __half* __restrict__ A, const float* __restrict__ bias) {
    __shared__ __half As[128][136];
    __shared__ __half Bs[32][72];
    __shared__ float Es[8][256];

    int tid = threadIdx.x;
    int lane = tid & 31;
    int wid = tid >> 5;
    int warp_m = wid & 3;
    int warp_n = wid >> 2;
    int row0 = blockIdx.x * 128;

    for (int idx = tid; idx < 2048; idx += 256) {
        int r = idx >> 4, c = (idx & 15) * 8;
        uint4 v = make_uint4(0, 0, 0, 0);
        if (row0 + r < N_NODES) v = *(const uint4*)&A[(size_t)(row0 + r) * 128 + c];
        *(uint4*)&As[r][c] = v;
    }
    __syncthreads();

    int r_ = lane >> 1, cb = (lane & 1) * 8;
    float sacc[2][3];
#pragma unroll
    for (int i = 0; i < 2; i++) { sacc[i][0] = 0.f; sacc[i][1] = 0.f; sacc[i][2] = 0.f; }

    for (int nb = 0; nb < 4; nb++) {
        int n0 = nb * 64;
        wmma::fragment<wmma::accumulator, 16, 16, 16, float> acc[2][2];
#pragma unroll
        for (int i = 0; i < 2; i++)
#pragma unroll
            for (int j = 0; j < 2; j++) wmma::fill_fragment(acc[i][j], 0.f);

        for (int kc = 0; kc < 128; kc += 32) {
            {
                int r = tid >> 3, c = (tid & 7) * 8;
                *(uint4*)&Bs[r][c] = *(const uint4*)&g_hW3[(kc + r) * 256 + n0 + c];
            }
            __syncthreads();
#pragma unroll
            for (int ks = 0; ks < 2; ks++) {
                wmma::fragment<wmma::matrix_a, 16, 16, 16, __half, wmma::row_major> af[2];
                wmma::fragment<wmma::matrix_b, 16, 16, 16, __half, wmma::row_major> bf[2];
#pragma unroll
                for (int i = 0; i < 2; i++)
                    wmma::load_matrix_sync(af[i], &As[warp_m * 32 + i * 16][kc + ks * 16], 136);
#pragma unroll
                for (int j = 0; j < 2; j++)
                    wmma::load_matrix_sync(bf[j], &Bs[ks * 16][warp_n * 32 + j * 16], 72);
#pragma unroll
                for (int i = 0; i < 2; i++)
#pragma unroll
                    for (int j = 0; j < 2; j++)
                        wmma::mma_sync(acc[i][j], af[i], bf[j], acc[i][j]);
            }
            __syncthreads();
        }

#pragma unroll
        for (int i = 0; i < 2; i++) {
#pragma unroll
            for (int j = 0; j < 2; j++) {
                wmma::store_matrix_sync(&Es[wid][0], acc[i][j], 16, wmma::mem_row_major);
                __syncwarp();
                int gc = n0 + warp_n * 32 + j * 16 + cb;
#pragma unroll
                for (int t = 0; t < 8; t++) {
                    float f = Es[wid][r_ * 16 + cb + t] + bias[gc + t];
                    f = fmaxf(f, 0.f);
                    sacc[i][0] += f * g_W45[(gc + t) * 3 + 0];
                    sacc[i][1] += f * g_W45[(gc + t) * 3 + 1];
                    sacc[i][2] += f * g_W45[(gc + t) * 3 + 2];
                }
                __syncwarp();
            }
        }
    }

    float* proj = (float*)Es;
    __syncthreads();
    for (int t = tid; t < 384; t += 256) proj[t] = 0.f;
    __syncthreads();
#pragma unroll
    for (int i = 0; i < 2; i++) {
        float s0 = sacc[i][0], s1 = sacc[i][1], s2 = sacc[i][2];
        s0 += __shfl_xor_sync(0xffffffffu, s0, 1);
        s1 += __shfl_xor_sync(0xffffffffu, s1, 1);
        s2 += __shfl_xor_sync(0xffffffffu, s2, 1);
        if ((lane & 1) == 0) {
            int rl = warp_m * 32 + i * 16 + r_;
            atomicAdd(&proj[rl * 3 + 0], s0);
            atomicAdd(&proj[rl * 3 + 1], s1);
            atomicAdd(&proj[rl * 3 + 2], s2);
        }
    }
    __syncthreads();
    for (int t = tid; t < 128; t += 256) {
        int node = row0 + t;
        if (node < N_NODES)
            g_proj[node] = make_float4(proj[t * 3 + 0], proj[t * 3 + 1], proj[t * 3 + 2], 0.f);
    }
}

// ---------------- aggregation D=64 fp16: 4 edges per warp (8 lanes x 16B each) ----------------
template <bool BIAS, bool RELU>
__global__ void k_agg64(const __half* __restrict__ H, const float* __restrict__ bias,
                        __half* __restrict__ out) {
    int warp = (blockIdx.x * blockDim.x + threadIdx.x) >> 5;
    int lane = threadIdx.x & 31;
    if (warp >= N_NODES) return;
    int grp = lane >> 3, gl = lane & 7;
    const uint4* H4 = (const uint4*)H;

    float a[8];
#pragma unroll
    for (int j = 0; j < 8; j++) a[j] = 0.f;

    if (grp == 0) {
        float selfn = g_dis[warp];
        selfn *= selfn;
        uint4 v = H4[(size_t)warp * 8 + gl];
        const __half2* h2 = (const __half2*)&v;
#pragma unroll
        for (int j = 0; j < 4; j++) {
            float2 f = __half22float2(h2[j]);
            a[2 * j] = f.x * selfn;
            a[2 * j + 1] = f.y * selfn;
        }
    }

    int s, e;
    unpack_row(__ldg(&g_rowcnt[warp]), s, e);
    for (int p = s + grp; p < e; p += 4) {
        int src; float w;
        unpack_edge(__ldg(&g_colval[p]), src, w);
        uint4 v = __ldg(&H4[(size_t)src * 8 + gl]);
        const __half2* h2 = (const __half2*)&v;
#pragma unroll
        for (int j = 0; j < 4; j++) {
            float2 f = __half22float2(h2[j]);
            a[2 * j] += f.x * w;
            a[2 * j + 1] += f.y * w;
        }
    }
    __syncwarp();
#pragma unroll
    for (int j = 0; j < 8; j++) {
        a[j] += __shfl_xor_sync(0xffffffffu, a[j], 8);
        a[j] += __shfl_xor_sync(0xffffffffu, a[j], 16);
    }
    if (grp == 0) {
#pragma unroll
        for (int j = 0; j < 8; j++) {
            if (BIAS) a[j] += bias[gl * 8 + j];
            if (RELU) a[j] = fmaxf(a[j], 0.f);
        }
        __half2 h0 = __floats2half2_rn(a[0], a[1]);
        __half2 h1 = __floats2half2_rn(a[2], a[3]);
        __half2 h2o = __floats2half2_rn(a[4], a[5]);
        __half2 h3 = __floats2half2_rn(a[6], a[7]);
        uint4 pk;
        pk.x = *(unsigned*)&h0; pk.y = *(unsigned*)&h1;
        pk.z = *(unsigned*)&h2o; pk.w = *(unsigned*)&h3;
        ((uint4*)out)[(size_t)warp * 8 + gl] = pk;
    }
}

// ---------------- aggregation D=128 fp16 in/out: 2 edges per warp (16 lanes x 16B) ----------------
__global__ void k_agg128(const __half* __restrict__ H, __half* __restrict__ out) {
    int warp = (blockIdx.x * blockDim.x + threadIdx.x) >> 5;
    int lane = threadIdx.x & 31;
    if (warp >= N_NODES) return;
    int half = lane >> 4, hl = lane & 15;
    const uint4* H4 = (const uint4*)H;

    float a[8];
#pragma unroll
    for (int j = 0; j < 8; j++) a[j] = 0.f;

    if (half == 0) {
        float selfn = g_dis[warp];
        selfn *= selfn;
        uint4 v = H4[(size_t)warp * 16 + hl];
        const __half2* h2 = (const __half2*)&v;
#pragma unroll
        for (int j = 0; j < 4; j++) {
            float2 f = __half22float2(h2[j]);
            a[2 * j] = f.x * selfn;
            a[2 * j + 1] = f.y * selfn;
        }
    }

    int s, e;
    unpack_row(__ldg(&g_rowcnt[warp]), s, e);
    for (int p = s + half; p < e; p += 2) {
        int src; float w;
        unpack_edge(__ldg(&g_colval[p]), src, w);
        uint4 v = __ldg(&H4[(size_t)src * 16 + hl]);
        const __half2* h2 = (const __half2*)&v;
#pragma unroll
        for (int j = 0; j < 4; j++) {
            float2 f = __half22float2(h2[j]);
            a[2 * j] += f.x * w;
            a[2 * j + 1] += f.y * w;
        }
    }
    __syncwarp();
#pragma unroll
    for (int j = 0; j < 8; j++)
        a[j] += __shfl_xor_sync(0xffffffffu, a[j], 16);
    if (half == 0) {
        __half2 h0 = __floats2half2_rn(a[0], a[1]);
        __half2 h1 = __floats2half2_rn(a[2], a[3]);
        __half2 h2o = __floats2half2_rn(a[4], a[5]);
        __half2 h3 = __floats2half2_rn(a[6], a[7]);
        uint4 pk;
        pk.x = *(unsigned*)&h0; pk.y = *(unsigned*)&h1;
        pk.z = *(unsigned*)&h2o; pk.w = *(unsigned*)&h3;
        ((uint4*)out)[(size_t)warp * 16 + hl] = pk;
    }
}

// ---------------- final aggregation at D=3 over g_proj ----------------
__global__ void k_agg3(float* __restrict__ out) {
    int v = blockIdx.x * blockDim.x + threadIdx.x;
    if (v >= N_NODES) return;
    float selfn = g_dis[v];
    selfn *= selfn;
    float4 p = g_proj[v];
    float a0 = p.x * selfn, a1 = p.y * selfn, a2 = p.z * selfn;

    int s, e;
    unpack_row(__ldg(&g_rowcnt[v]), s, e);
#pragma unroll 2
    for (int q = s; q < e; q++) {
        int src; float w;
        unpack_edge(__ldg(&g_colval[q]), src, w);
        float4 h = __ldg(&g_proj[src]);
        a0 += h.x * w; a1 += h.y * w; a2 += h.z * w;
    }
    out[(size_t)v * 3 + 0] = a0 + g_b45[0];
    out[(size_t)v * 3 + 1] = a1 + g_b45[1];
    out[(size_t)v * 3 + 2] = a2 + g_b45[2];
}

// ---------------- launch ----------------
extern "C" void kernel_launch(void* const* d_in, const int* in_sizes, int n_in,
                              void* d_out, int out_size) {
    const float* x    = (const float*)d_in[0];
    const void*  ei   = d_in[1];
    const float* ew   = (const float*)d_in[2];
    const float* W1   = (const float*)d_in[3];
    const float* b1   = (const float*)d_in[4];
    const float* W2   = (const float*)d_in[5];
    const float* b2   = (const float*)d_in[6];
    const float* W3   = (const float*)d_in[7];
    const float* b3   = (const float*)d_in[8];
    const float* W4   = (const float*)d_in[9];
    const float* b4   = (const float*)d_in[10];
    const float* Wout = (const float*)d_in[11];
    const float* bout = (const float*)d_in[12];
    float* out = (float*)d_out;

    __half *hA, *hB, *hW1, *hW2, *hW3;
    cudaGetSymbolAddress((void**)&hA, g_hA);
    cudaGetSymbolAddress((void**)&hB, g_hB);
    cudaGetSymbolAddress((void**)&hW1, g_hW1);
    cudaGetSymbolAddress((void**)&hW2, g_hW2);
    cudaGetSymbolAddress((void**)&hW3, g_hW3);

    static cudaStream_t s2 = nullptr;
    static cudaEvent_t evFork = nullptr, evJoin = nullptr, evJoin2 = nullptr;
    if (!s2) {
        cudaStreamCreateWithFlags(&s2, cudaStreamNonBlocking);
        cudaEventCreateWithFlags(&evFork, cudaEventDisableTiming);
        cudaEventCreateWithFlags(&evJoin, cudaEventDisableTiming);
        cudaEventCreateWithFlags(&evJoin2, cudaEventDisableTiming);
    }

    const int TB = 256;
    int nodeBlocks = (N_NODES + TB - 1) / TB;
    int edgeBlocks = (N_EDGES + TB - 1) / TB;
    int warpNodeBlocks = (N_NODES + 7) / 8;
    int gm = (N_NODES + 127) / 128;
    int cvtBlocks = (49152 / 8 + TB - 1) / TB;

    // fork: weight conversion + GEMM1 (reads x fp32 directly); W45 fold before fused L3
    cudaEventRecord(evFork, 0);
    cudaStreamWaitEvent(s2, evFork, 0);
    k_cvtw<<<cvtBlocks, TB, 0, s2>>>(W1, W2, W3, hW1, hW2, hW3);
    k_hgemm<true><<<dim3(gm, 1), 256, 0, s2>>>(x, hW1, nullptr, hA, 128, 64, 0);
    cudaEventRecord(evJoin, s2);
    k_w45<<<97, 256, 0, s2>>>(W4, b4, Wout, bout);
    cudaEventRecord(evJoin2, s2);

    // main stream: CSR preprocessing (4 kernels)
    k_initdet<<<nodeBlocks, TB>>>((const long long*)ei);
    k_decdeg<<<edgeBlocks, TB>>>(ei, ew);
    k_disalloc<<<nodeBlocks, TB>>>();
    k_build<<<edgeBlocks, TB>>>(ei, ew);

    cudaStreamWaitEvent(0, evJoin, 0);

    // L1: h1 = relu(agg(t1) + b1)
    k_agg64<true, true><<<warpNodeBlocks, 256>>>(hA, b1, hB);

    // L2: h2 = relu(agg(h1) @ W2 + b2)
    k_agg64<false, false><<<warpNodeBlocks, 256>>>(hB, nullptr, hA);
    k_hgemm<false><<<dim3(gm, 2), 256>>>(hA, hW2, b2, hB, 64, 128, 1);

    // L3 + proj fused: g_proj = relu(agg(h2) @ W3 + b3) @ W45   (h3 never materialized)
    k_agg128<<<warpNodeBlocks, 256>>>(hB, hA);
    cudaStreamWaitEvent(0, evJoin2, 0);          // W45 ready
    k_hgemm_proj<<<gm, 256>>>(hA, b3);

    // L4 head: out = agg(g_proj) + b45
    k_agg3<<<nodeBlocks, TB>>>(out);

    (void)in_sizes; (void)n_in; (void)out_size;
}